// round 10
// baseline (speedup 1.0000x reference)
#include <cuda_runtime.h>
#include <cstdint>

// Problem constants
#define B_ 8
#define T_ 2048
#define D_ 1024
#define M_ (B_ * T_)          // 16384
#define EPS_WKV 1e-9f
#define EPS_GN  1e-5f
#define CH_ 16                 // scan chunks
#define L_ (T_ / CH_)          // 128 steps per chunk

// perm16 (involution): within each 16-group, position p holds k with
// p = 4*(k&3) + ((k>>2)&3).  One float4 at pos 4j = k {j, j+4, j+8, j+12}.
#define PERM16(k) (((k) & ~15) | (((k) & 3) << 2) | (((k) >> 2) & 3))

// -------------------- device scratch (no allocations allowed) --------------------
__device__ float g_XR[(size_t)M_ * D_];   // xr mix (perm16 cols); later scan output (perm16)
__device__ float g_XK[(size_t)M_ * D_];   // perm16 cols
__device__ float g_XV[(size_t)M_ * D_];   // perm16 cols
__device__ float g_R [(size_t)M_ * D_];   // natural cols (GEMM outputs)
__device__ float g_EK[(size_t)M_ * D_];
__device__ float g_V [(size_t)M_ * D_];
__device__ float g_Wr[(size_t)D_ * D_];   // tf32-rounded, perm16 cols
__device__ float g_Wk[(size_t)D_ * D_];
__device__ float g_Wv[(size_t)D_ * D_];
__device__ float g_Wg[(size_t)D_ * D_];   // tf32(gamma ⊙ W_o), perm16 cols
__device__ float g_c1[D_];
__device__ float g_c2[D_];
__device__ float g_locN[CH_ * B_ * 1024];
__device__ float g_locD[CH_ * B_ * 1024];
__device__ float g_carN[CH_ * B_ * 1024];
__device__ float g_carD[CH_ * B_ * 1024];
__device__ float g_part[8192];
__device__ float g_stats[16];

// -------------------- helpers --------------------
__device__ __forceinline__ float tf32r(float f) {
    uint32_t u;
    asm("cvt.rna.tf32.f32 %0, %1;" : "=r"(u) : "f"(f));
    return __uint_as_float(u);
}
__device__ __forceinline__ void cp16(uint32_t dst, const void* src) {
    asm volatile("cp.async.cg.shared.global [%0], [%1], 16;" :: "r"(dst), "l"(src) : "memory");
}
__device__ __forceinline__ uint32_t smem_u32(const void* p) {
    uint32_t a;
    asm("{ .reg .u64 t; cvta.to.shared.u64 t, %1; cvt.u32.u64 %0, t; }" : "=r"(a) : "l"(p));
    return a;
}
__device__ __forceinline__ void mma_tf32(float* c, const uint32_t* a, const uint32_t* b) {
    asm volatile(
        "mma.sync.aligned.m16n8k8.row.col.f32.tf32.tf32.f32 "
        "{%0,%1,%2,%3}, {%4,%5,%6,%7}, {%8,%9}, {%0,%1,%2,%3};"
        : "+f"(c[0]), "+f"(c[1]), "+f"(c[2]), "+f"(c[3])
        : "r"(a[0]), "r"(a[1]), "r"(a[2]), "r"(a[3]), "r"(b[0]), "r"(b[1]));
}
#define U32F(x) __float_as_uint(x)

// -------------------- 1) token-shift + time-mix; tf32-rounded, perm16 output --------------------
// 16 channels per thread; in-register 4x4 transpose for the permuted store.
__global__ void mix_kernel(const float* __restrict__ x, const float* __restrict__ state,
                           const float* __restrict__ mr, const float* __restrict__ mk,
                           const float* __restrict__ mv)
{
    int i16 = blockIdx.x * blockDim.x + threadIdx.x;
    int elem = i16 * 16;
    int d = elem & (D_ - 1);
    int t = (elem >> 10) & (T_ - 1);

    float xv[16], pv[16];
#pragma unroll
    for (int i = 0; i < 4; i++) {
        float4 v = *(const float4*)(x + elem + 4 * i);
        xv[4*i] = v.x; xv[4*i+1] = v.y; xv[4*i+2] = v.z; xv[4*i+3] = v.w;
    }
    if (t == 0) {
        int b = elem >> 21;
        int s0 = ((b << 10) + d) * 3 + 2;
#pragma unroll
        for (int i = 0; i < 16; i++) pv[i] = state[s0 + 3 * i];
    } else {
#pragma unroll
        for (int i = 0; i < 4; i++) {
            float4 v = *(const float4*)(x + elem - D_ + 4 * i);
            pv[4*i] = v.x; pv[4*i+1] = v.y; pv[4*i+2] = v.z; pv[4*i+3] = v.w;
        }
    }

#define MIX16(WPTR, DST)                                                        \
    {                                                                           \
        float ov[16];                                                           \
        _Pragma("unroll")                                                       \
        for (int i = 0; i < 4; i++) {                                           \
            float4 w = *(const float4*)(WPTR + d + 4 * i);                      \
            ov[4*i+0] = tf32r(xv[4*i+0] * w.x + pv[4*i+0] * (1.f - w.x));       \
            ov[4*i+1] = tf32r(xv[4*i+1] * w.y + pv[4*i+1] * (1.f - w.y));       \
            ov[4*i+2] = tf32r(xv[4*i+2] * w.z + pv[4*i+2] * (1.f - w.z));       \
            ov[4*i+3] = tf32r(xv[4*i+3] * w.w + pv[4*i+3] * (1.f - w.w));       \
        }                                                                       \
        _Pragma("unroll")                                                       \
        for (int j = 0; j < 4; j++) {                                           \
            float4 o;                                                           \
            o.x = ov[j]; o.y = ov[4 + j]; o.z = ov[8 + j]; o.w = ov[12 + j];    \
            *(float4*)(DST + elem + 4 * j) = o;                                 \
        }                                                                       \
    }
    MIX16(mr, g_XR)
    MIX16(mk, g_XK)
    MIX16(mv, g_XV)
#undef MIX16
}

// -------------------- 1b) tf32-rounded, perm16 weight copies --------------------
__global__ void round_w(const float* __restrict__ Wr, const float* __restrict__ Wk,
                        const float* __restrict__ Wv)
{
    int e = (blockIdx.x * blockDim.x + threadIdx.x) * 16;
#define RW16(SRC, DST)                                                          \
    {                                                                           \
        float av[16];                                                           \
        _Pragma("unroll")                                                       \
        for (int i = 0; i < 4; i++) {                                           \
            float4 v = *(const float4*)(SRC + e + 4 * i);                       \
            av[4*i+0] = tf32r(v.x); av[4*i+1] = tf32r(v.y);                     \
            av[4*i+2] = tf32r(v.z); av[4*i+3] = tf32r(v.w);                     \
        }                                                                       \
        _Pragma("unroll")                                                       \
        for (int j = 0; j < 4; j++) {                                           \
            float4 o;                                                           \
            o.x = av[j]; o.y = av[4 + j]; o.z = av[8 + j]; o.w = av[12 + j];    \
            *(float4*)(DST + e + 4 * j) = o;                                    \
        }                                                                       \
    }
    RW16(Wr, g_Wr)
    RW16(Wk, g_Wk)
    RW16(Wv, g_Wv)
#undef RW16
}

// -------------------- 1c) fold GroupNorm affine into W_o (perm16 store) --------------------
__global__ void prep_wo(const float* __restrict__ Wo, const float* __restrict__ gam,
                        const float* __restrict__ bet)
{
    __shared__ float sh1[8], sh2[8];
    int n = blockIdx.x;
    float s1 = 0.f, s2 = 0.f;
    for (int k = threadIdx.x; k < D_; k += 256) {
        float w = Wo[n * D_ + k];
        float wg = tf32r(gam[k] * w);
        g_Wg[(size_t)n * D_ + PERM16(k)] = wg;
        s1 += wg;
        s2 += bet[k] * w;
    }
#pragma unroll
    for (int off = 16; off; off >>= 1) {
        s1 += __shfl_down_sync(0xffffffffu, s1, off);
        s2 += __shfl_down_sync(0xffffffffu, s2, off);
    }
    if ((threadIdx.x & 31) == 0) { sh1[threadIdx.x >> 5] = s1; sh2[threadIdx.x >> 5] = s2; }
    __syncthreads();
    if (threadIdx.x == 0) {
        float a = 0.f, b = 0.f;
        for (int i = 0; i < 8; i++) { a += sh1[i]; b += sh2[i]; }  // fixed order
        g_c1[n] = a; g_c2[n] = b;
    }
}

// -------------------- 2) tf32 mma.sync GEMM core (LDS.128 fragments, parity swizzle) --------
constexpr int BKt = 32;
constexpr int NIT = D_ / BKt;                  // 32
constexpr int TILE_FLOATS = 128 * 32;          // 16KB
constexpr int STAGE_FLOATS = 2 * TILE_FLOATS;
constexpr int STAGE_BYTES = STAGE_FLOATS * 4;  // 32768
constexpr int STAGES = 3;
constexpr int SMEM_SZ = STAGES * STAGE_BYTES;  // 98304

__device__ __forceinline__ void gemm_body(const float* __restrict__ A, const float* __restrict__ W,
                                          float* smf, uint32_t sb, int m0, int n0,
                                          float c[2][8][4])
{
    const int tid = threadIdx.x;
    const int lane = tid & 31;
    const int wid = tid >> 5;
    const int lr = lane >> 2, lc = lane & 3;
    const int wm = wid & 3, wn = wid >> 2;

#pragma unroll
    for (int mi = 0; mi < 2; mi++)
#pragma unroll
        for (int ni = 0; ni < 8; ni++)
#pragma unroll
            for (int q = 0; q < 4; q++) c[mi][ni][q] = 0.f;

    auto load_stage = [&](int it, int s) {
        int kt = it * BKt;
        uint32_t ab = sb + s * STAGE_BYTES;
        uint32_t bb = ab + TILE_FLOATS * 4;
#pragma unroll
        for (int i = 0; i < 4; i++) {
            int g = tid + i * 256;
            int row = g >> 3;
            int c4 = g & 7;
            int swc = c4 ^ ((row & 1) << 2);           // parity swizzle
            uint32_t off = row * 128 + swc * 16;
            cp16(ab + off, A + (size_t)(m0 + row) * D_ + kt + c4 * 4);
            cp16(bb + off, W + (size_t)(n0 + row) * D_ + kt + c4 * 4);
        }
        asm volatile("cp.async.commit_group;" ::: "memory");
    };

    load_stage(0, 0);
    load_stage(1, 1);
    asm volatile("cp.async.wait_group 1;" ::: "memory");
    __syncthreads();

    const int pxor = (lr & 1) << 2;                    // all fragment rows share parity lr&1

    for (int kt = 0; kt < NIT; kt++) {
        int s = kt % STAGES;
        if (kt + 2 < NIT) load_stage(kt + 2, (kt + 2) % STAGES);

        const float* As = smf + s * STAGE_FLOATS;
        const float* Bs = As + TILE_FLOATS;
#pragma unroll
        for (int k16 = 0; k16 < 2; k16++) {
            const int ck = ((k16 << 2) + lc) ^ pxor;   // chunk 0..7
            const float* Afr = As + lr * 32 + ck * 4;
            const float* Bfr = Bs + (wn * 64 + lr) * 32 + ck * 4;

            // A fragments for both k-steps: 4x LDS.128
            float4 alo0 = *(const float4*)(Afr + (wm * 32 +  0) * 32);
            float4 ahi0 = *(const float4*)(Afr + (wm * 32 +  8) * 32);
            float4 alo1 = *(const float4*)(Afr + (wm * 32 + 16) * 32);
            float4 ahi1 = *(const float4*)(Afr + (wm * 32 + 24) * 32);
            uint32_t a00[4] = {U32F(alo0.x), U32F(ahi0.x), U32F(alo0.y), U32F(ahi0.y)};
            uint32_t a01[4] = {U32F(alo1.x), U32F(ahi1.x), U32F(alo1.y), U32F(ahi1.y)};
            uint32_t a10[4] = {U32F(alo0.z), U32F(ahi0.z), U32F(alo0.w), U32F(ahi0.w)};
            uint32_t a11[4] = {U32F(alo1.z), U32F(ahi1.z), U32F(alo1.w), U32F(ahi1.w)};

#pragma unroll
            for (int ni = 0; ni < 8; ni++) {
                float4 bv = *(const float4*)(Bfr + ni * 8 * 32);   // 1x LDS.128, 2 k-steps
                uint32_t b0[2] = {U32F(bv.x), U32F(bv.y)};
                uint32_t b1[2] = {U32F(bv.z), U32F(bv.w)};
                mma_tf32(c[0][ni], a00, b0);
                mma_tf32(c[1][ni], a01, b0);
                mma_tf32(c[0][ni], a10, b1);
                mma_tf32(c[1][ni], a11, b1);
            }
        }

        if (kt < NIT - 1) {
            if (kt + 2 < NIT) asm volatile("cp.async.wait_group 1;" ::: "memory");
            else              asm volatile("cp.async.wait_group 0;" ::: "memory");
            __syncthreads();
        }
    }
}

// Fused r/k/v GEMMs: blockIdx.z selects mode 0(sigmoid->g_R) 1(exp->g_EK) 2(->g_V)
__global__ void __launch_bounds__(256, 2)
gemm_qkv()
{
    extern __shared__ float smf[];
    uint32_t sb = smem_u32(smf);
    const int mode = blockIdx.z;
    const int m0 = blockIdx.y * 128;
    const int n0 = blockIdx.x * 128;
    const float* A = (mode == 0) ? g_XR : (mode == 1) ? g_XK : g_XV;
    const float* W = (mode == 0) ? g_Wr : (mode == 1) ? g_Wk : g_Wv;
    float* C = (mode == 0) ? g_R : (mode == 1) ? g_EK : g_V;

    float c[2][8][4];
    gemm_body(A, W, smf, sb, m0, n0, c);

    const int lane = threadIdx.x & 31;
    const int wid = threadIdx.x >> 5;
    const int lr = lane >> 2, lc = lane & 3;
    const int wm = wid & 3, wn = wid >> 2;
#pragma unroll
    for (int mi = 0; mi < 2; mi++) {
#pragma unroll
        for (int half = 0; half < 2; half++) {
            int m = m0 + wm * 32 + mi * 16 + lr + half * 8;
            float* crow = C + (size_t)m * D_ + n0 + wn * 64 + lc * 2;
#pragma unroll
            for (int ni = 0; ni < 8; ni++) {
                float v0 = c[mi][ni][half * 2 + 0];
                float v1 = c[mi][ni][half * 2 + 1];
                float2 o;
                if (mode == 0) {
                    o.x = 1.f / (1.f + __expf(-v0));
                    o.y = 1.f / (1.f + __expf(-v1));
                } else if (mode == 1) {
                    o.x = __expf(v0); o.y = __expf(v1);
                } else {
                    o.x = v0; o.y = v1;
                }
                *(float2*)(crow + ni * 8) = o;
            }
        }
    }
}

// Final GEMM: out = (scan_out normalized) @ (gamma⊙Wo)^T, GN folded algebraically
__global__ void __launch_bounds__(256, 2)
gemm_o(float* __restrict__ Cout)
{
    extern __shared__ float smf[];
    uint32_t sb = smem_u32(smf);
    const int m0 = blockIdx.y * 128;
    const int n0 = blockIdx.x * 128;

    float c[2][8][4];
    gemm_body(g_XR, g_Wg, smf, sb, m0, n0, c);

    const int lane = threadIdx.x & 31;
    const int wid = threadIdx.x >> 5;
    const int lr = lane >> 2, lc = lane & 3;
    const int wm = wid & 3, wn = wid >> 2;

    int b = m0 / T_;
    float mu = g_stats[2 * b];
    float rstd = g_stats[2 * b + 1];
#pragma unroll
    for (int mi = 0; mi < 2; mi++) {
#pragma unroll
        for (int half = 0; half < 2; half++) {
            int m = m0 + wm * 32 + mi * 16 + lr + half * 8;
            float* crow = Cout + (size_t)m * D_ + n0 + wn * 64 + lc * 2;
#pragma unroll
            for (int ni = 0; ni < 8; ni++) {
                float v0 = c[mi][ni][half * 2 + 0];
                float v1 = c[mi][ni][half * 2 + 1];
                int n = n0 + wn * 64 + ni * 8 + lc * 2;
                float2 o;
                o.x = v0 * rstd + (g_c2[n + 0] - mu * rstd * g_c1[n + 0]);
                o.y = v1 * rstd + (g_c2[n + 1] - mu * rstd * g_c1[n + 1]);
                *(float2*)(crow + ni * 8) = o;
            }
        }
    }
}

// -------------------- 3) chunk-parallel WKV scan --------------------
__global__ void scan_part1(const float* __restrict__ decay)
{
    int g = blockIdx.x * blockDim.x + threadIdx.x;
    int c = g & 1023;
    int cb = g >> 10;
    int b = cb & 7;
    int chunk = cb >> 3;

    float w = __expf(-__expf(decay[c]));
    const float* pEK = g_EK + ((size_t)(b * T_ + chunk * L_)) * D_ + c;
    const float* pV  = g_V  + ((size_t)(b * T_ + chunk * L_)) * D_ + c;

    float num = 0.f, den = 0.f;
#pragma unroll 4
    for (int t = 0; t < L_; t++) {
        float ek = pEK[(size_t)t * D_];
        float v  = pV [(size_t)t * D_];
        num = num * w + ek * v;
        den = den * w + ek;
    }
    g_locN[g] = num;
    g_locD[g] = den;
}

__global__ void scan_part2(const float* __restrict__ state, const float* __restrict__ decay)
{
    int g = blockIdx.x * blockDim.x + threadIdx.x;     // 0..8191
    int c = g & 1023;
    int b = g >> 10;
    float wL = __expf(-__expf(decay[c]) * (float)L_);
    float cn = state[((b << 10) + c) * 3 + 0];
    float cd = state[((b << 10) + c) * 3 + 1];
#pragma unroll
    for (int chunk = 0; chunk < CH_; chunk++) {
        int idx = ((chunk << 3) + b) * 1024 + c;
        g_carN[idx] = cn;
        g_carD[idx] = cd;
        cn = cn * wL + g_locN[idx];
        cd = cd * wL + g_locD[idx];
    }
}

__global__ void scan_part3(const float* __restrict__ decay, const float* __restrict__ first)
{
    int g = blockIdx.x * blockDim.x + threadIdx.x;
    int c = g & 1023;
    int cb = g >> 10;
    int b = cb & 7;
    int chunk = cb >> 3;

    float w  = __expf(-__expf(decay[c]));
    float eu = __expf(first[c]);
    float num = g_carN[g];
    float den = g_carD[g];

    size_t base = ((size_t)(b * T_ + chunk * L_)) * D_;
    const float* pR  = g_R  + base + c;
    const float* pEK = g_EK + base + c;
    const float* pV  = g_V  + base + c;
    int cp = PERM16(c);                                // permuted column for GEMM-4 input
    float*       pO  = g_XR + base + cp;

    float sum = 0.f, sq = 0.f;
#pragma unroll 4
    for (int t = 0; t < L_; t++) {
        float ek = pEK[(size_t)t * D_];
        float v  = pV [(size_t)t * D_];
        float r  = pR [(size_t)t * D_];
        float ee = eu * ek;
        float wkv = __fdividef(num + ee * v, den + ee + EPS_WKV);
        float o = tf32r(r * wkv);
        pO[(size_t)t * D_] = o;
        sum += o;
        sq  += o * o;
        num = num * w + ek * v;
        den = den * w + ek;
    }
#pragma unroll
    for (int off = 16; off; off >>= 1) {
        sum += __shfl_down_sync(0xffffffffu, sum, off);
        sq  += __shfl_down_sync(0xffffffffu, sq,  off);
    }
    if ((threadIdx.x & 31) == 0) {
        int wg = g >> 5;
        g_part[wg * 2 + 0] = sum;
        g_part[wg * 2 + 1] = sq;
    }
}

__global__ void stats_kernel()
{
    int b = blockIdx.x;
    int lane = threadIdx.x;
    float s = 0.f, q = 0.f;
#pragma unroll
    for (int chunk = 0; chunk < CH_; chunk++) {
        int idx = chunk * 256 + b * 32 + lane;
        s += g_part[idx * 2 + 0];
        q += g_part[idx * 2 + 1];
    }
#pragma unroll
    for (int off = 16; off; off >>= 1) {
        s += __shfl_down_sync(0xffffffffu, s, off);
        q += __shfl_down_sync(0xffffffffu, q, off);
    }
    if (lane == 0) {
        const float N = (float)(T_ * D_);
        float mu = s / N;
        float var = q / N - mu * mu;
        g_stats[2 * b + 0] = mu;
        g_stats[2 * b + 1] = rsqrtf(var + EPS_GN);
    }
}

// -------------------- launch --------------------
extern "C" void kernel_launch(void* const* d_in, const int* in_sizes, int n_in,
                              void* d_out, int out_size)
{
    (void)in_sizes; (void)n_in; (void)out_size;
    const float* x     = (const float*)d_in[0];
    const float* state = (const float*)d_in[1];
    const float* Wr    = (const float*)d_in[2];
    const float* Wk    = (const float*)d_in[3];
    const float* Wv    = (const float*)d_in[4];
    const float* Wo    = (const float*)d_in[5];
    const float* mr    = (const float*)d_in[6];
    const float* mk    = (const float*)d_in[7];
    const float* mv    = (const float*)d_in[8];
    const float* decay = (const float*)d_in[9];
    const float* first = (const float*)d_in[10];
    const float* gam   = (const float*)d_in[11];
    const float* bet   = (const float*)d_in[12];
    float* out = (float*)d_out;

    cudaFuncSetAttribute(gemm_qkv, cudaFuncAttributeMaxDynamicSharedMemorySize, SMEM_SZ);
    cudaFuncSetAttribute(gemm_o,   cudaFuncAttributeMaxDynamicSharedMemorySize, SMEM_SZ);

    const int MIX_BLOCKS = (M_ * D_ / 16) / 256;
    const int RW_BLOCKS  = (D_ * D_ / 16) / 256;
    const int S13_BLOCKS = (CH_ * B_ * 1024) / 256;
    const int S2_BLOCKS  = (B_ * 1024) / 256;

    round_w<<<RW_BLOCKS, 256>>>(Wr, Wk, Wv);
    prep_wo<<<D_, 256>>>(Wo, gam, bet);
    mix_kernel<<<MIX_BLOCKS, 256>>>(x, state, mr, mk, mv);

    dim3 gq(D_ / 128, M_ / 128, 3);          // fused r/k/v GEMMs
    gemm_qkv<<<gq, 256, SMEM_SZ>>>();

    scan_part1<<<S13_BLOCKS, 256>>>(decay);
    scan_part2<<<S2_BLOCKS, 256>>>(state, decay);
    scan_part3<<<S13_BLOCKS, 256>>>(decay, first);
    stats_kernel<<<8, 32>>>();

    dim3 gg(D_ / 128, M_ / 128);
    gemm_o<<<gg, 256, SMEM_SZ>>>(out);
}

// round 11
// speedup vs baseline: 1.2326x; 1.2326x over previous
#include <cuda_runtime.h>
#include <cstdint>

// Problem constants
#define B_ 8
#define T_ 2048
#define D_ 1024
#define M_ (B_ * T_)          // 16384
#define EPS_WKV 1e-9f
#define EPS_GN  1e-5f
#define CH_ 16                 // scan chunks
#define L_ (T_ / CH_)          // 128 steps per chunk

// k-permutation within each 8-group: pos p holds k = [0,4,1,5,2,6,3,7][p]
// perm(k) = (k&~7) | (2*(k&3) + ((k>>2)&1))

// -------------------- device scratch (no allocations allowed) --------------------
__device__ float g_XR[(size_t)M_ * D_];   // xr mix (perm cols); later scan output (perm cols)
__device__ float g_XK[(size_t)M_ * D_];   // perm cols
__device__ float g_XV[(size_t)M_ * D_];   // perm cols
__device__ float g_R [(size_t)M_ * D_];   // natural cols (GEMM outputs)
__device__ float g_EK[(size_t)M_ * D_];
__device__ float g_V [(size_t)M_ * D_];
__device__ float g_Wr[(size_t)D_ * D_];   // tf32-rounded, perm cols
__device__ float g_Wk[(size_t)D_ * D_];
__device__ float g_Wv[(size_t)D_ * D_];
__device__ float g_Wg[(size_t)D_ * D_];   // tf32(gamma ⊙ W_o), perm cols
__device__ float g_c1[D_];
__device__ float g_c2[D_];
__device__ float g_locN[CH_ * B_ * 1024];
__device__ float g_locD[CH_ * B_ * 1024];
__device__ float g_carN[CH_ * B_ * 1024];
__device__ float g_carD[CH_ * B_ * 1024];
__device__ float g_part[8192];
__device__ float g_stats[16];

// -------------------- helpers --------------------
__device__ __forceinline__ float tf32r(float f) {
    uint32_t u;
    asm("cvt.rna.tf32.f32 %0, %1;" : "=r"(u) : "f"(f));
    return __uint_as_float(u);
}
__device__ __forceinline__ void cp16(uint32_t dst, const void* src) {
    asm volatile("cp.async.cg.shared.global [%0], [%1], 16;" :: "r"(dst), "l"(src) : "memory");
}
__device__ __forceinline__ uint32_t smem_u32(const void* p) {
    uint32_t a;
    asm("{ .reg .u64 t; cvta.to.shared.u64 t, %1; cvt.u32.u64 %0, t; }" : "=r"(a) : "l"(p));
    return a;
}
__device__ __forceinline__ void mma_tf32(float* c, const uint32_t* a, const uint32_t* b) {
    asm volatile(
        "mma.sync.aligned.m16n8k8.row.col.f32.tf32.tf32.f32 "
        "{%0,%1,%2,%3}, {%4,%5,%6,%7}, {%8,%9}, {%0,%1,%2,%3};"
        : "+f"(c[0]), "+f"(c[1]), "+f"(c[2]), "+f"(c[3])
        : "r"(a[0]), "r"(a[1]), "r"(a[2]), "r"(a[3]), "r"(b[0]), "r"(b[1]));
}
#define U32F(x) __float_as_uint(x)

// -------------------- 1) token-shift + time-mix; outputs tf32-rounded, k-permuted --------------------
__global__ void mix_kernel(const float* __restrict__ x, const float* __restrict__ state,
                           const float* __restrict__ mr, const float* __restrict__ mk,
                           const float* __restrict__ mv)
{
    int i8 = blockIdx.x * blockDim.x + threadIdx.x;
    int elem = i8 * 8;
    int d = elem & (D_ - 1);
    int t = (elem >> 10) & (T_ - 1);

    float4 x0 = *(const float4*)(x + elem);
    float4 x1 = *(const float4*)(x + elem + 4);
    float4 p0, p1;
    if (t == 0) {
        int b = elem >> 21;
        int s0 = ((b << 10) + d) * 3 + 2;
        p0.x = state[s0 + 0];  p0.y = state[s0 + 3];
        p0.z = state[s0 + 6];  p0.w = state[s0 + 9];
        p1.x = state[s0 + 12]; p1.y = state[s0 + 15];
        p1.z = state[s0 + 18]; p1.w = state[s0 + 21];
    } else {
        p0 = *(const float4*)(x + elem - D_);
        p1 = *(const float4*)(x + elem - D_ + 4);
    }

#define MIX8(WPTR, DST)                                                          \
    {                                                                            \
        float4 w0 = *(const float4*)(WPTR + d);                                  \
        float4 w1 = *(const float4*)(WPTR + d + 4);                              \
        float o0 = tf32r(x0.x * w0.x + p0.x * (1.f - w0.x));                     \
        float o1 = tf32r(x0.y * w0.y + p0.y * (1.f - w0.y));                     \
        float o2 = tf32r(x0.z * w0.z + p0.z * (1.f - w0.z));                     \
        float o3 = tf32r(x0.w * w0.w + p0.w * (1.f - w0.w));                     \
        float o4 = tf32r(x1.x * w1.x + p1.x * (1.f - w1.x));                     \
        float o5 = tf32r(x1.y * w1.y + p1.y * (1.f - w1.y));                     \
        float o6 = tf32r(x1.z * w1.z + p1.z * (1.f - w1.z));                     \
        float o7 = tf32r(x1.w * w1.w + p1.w * (1.f - w1.w));                     \
        float4 s0v; s0v.x = o0; s0v.y = o4; s0v.z = o1; s0v.w = o5;              \
        float4 s1v; s1v.x = o2; s1v.y = o6; s1v.z = o3; s1v.w = o7;              \
        *(float4*)(DST + elem) = s0v;                                            \
        *(float4*)(DST + elem + 4) = s1v;                                        \
    }
    MIX8(mr, g_XR)
    MIX8(mk, g_XK)
    MIX8(mv, g_XV)
#undef MIX8
}

// -------------------- 1b) tf32-rounded, k-permuted weight copies --------------------
__global__ void round_w(const float* __restrict__ Wr, const float* __restrict__ Wk,
                        const float* __restrict__ Wv)
{
    int e = (blockIdx.x * blockDim.x + threadIdx.x) * 8;
#define RW8(SRC, DST)                                                            \
    {                                                                            \
        float4 a0 = *(const float4*)(SRC + e);                                   \
        float4 a1 = *(const float4*)(SRC + e + 4);                               \
        float4 s0v; float4 s1v;                                                  \
        s0v.x = tf32r(a0.x); s0v.y = tf32r(a1.x);                                \
        s0v.z = tf32r(a0.y); s0v.w = tf32r(a1.y);                                \
        s1v.x = tf32r(a0.z); s1v.y = tf32r(a1.z);                                \
        s1v.z = tf32r(a0.w); s1v.w = tf32r(a1.w);                                \
        *(float4*)(DST + e) = s0v;                                               \
        *(float4*)(DST + e + 4) = s1v;                                           \
    }
    RW8(Wr, g_Wr)
    RW8(Wk, g_Wk)
    RW8(Wv, g_Wv)
#undef RW8
}

// -------------------- 1c) fold GroupNorm affine into W_o (k-permuted store) --------------------
__global__ void prep_wo(const float* __restrict__ Wo, const float* __restrict__ gam,
                        const float* __restrict__ bet)
{
    __shared__ float sh1[8], sh2[8];
    int n = blockIdx.x;
    float s1 = 0.f, s2 = 0.f;
    for (int k = threadIdx.x; k < D_; k += 256) {
        float w = Wo[n * D_ + k];
        float wg = tf32r(gam[k] * w);
        int kp = (k & ~7) | (2 * (k & 3) + ((k >> 2) & 1));
        g_Wg[(size_t)n * D_ + kp] = wg;
        s1 += wg;
        s2 += bet[k] * w;
    }
#pragma unroll
    for (int off = 16; off; off >>= 1) {
        s1 += __shfl_down_sync(0xffffffffu, s1, off);
        s2 += __shfl_down_sync(0xffffffffu, s2, off);
    }
    if ((threadIdx.x & 31) == 0) { sh1[threadIdx.x >> 5] = s1; sh2[threadIdx.x >> 5] = s2; }
    __syncthreads();
    if (threadIdx.x == 0) {
        float a = 0.f, b = 0.f;
        for (int i = 0; i < 8; i++) { a += sh1[i]; b += sh2[i]; }  // fixed order
        g_c1[n] = a; g_c2[n] = b;
    }
}

// -------------------- 2) tf32 mma.sync GEMM core (R9 body + hoisted addressing) ------------
constexpr int BKt = 32;
constexpr int NIT = D_ / BKt;                  // 32
constexpr int TILE_FLOATS = 128 * 32;          // 16KB
constexpr int STAGE_FLOATS = 2 * TILE_FLOATS;
constexpr int STAGE_BYTES = STAGE_FLOATS * 4;  // 32768
constexpr int STAGES = 3;
constexpr int SMEM_SZ = STAGES * STAGE_BYTES;  // 98304
constexpr uint32_t RING_TOP = (STAGES - 1) * STAGE_BYTES;

__device__ __forceinline__ void gemm_body(const float* __restrict__ A, const float* __restrict__ W,
                                          float* smf, uint32_t sb, int m0, int n0,
                                          float c[2][8][4])
{
    const int tid = threadIdx.x;
    const int lane = tid & 31;
    const int wid = tid >> 5;
    const int lr = lane >> 2, lc = lane & 3;
    const int wm = wid & 3, wn = wid >> 2;

#pragma unroll
    for (int mi = 0; mi < 2; mi++)
#pragma unroll
        for (int ni = 0; ni < 8; ni++)
#pragma unroll
            for (int q = 0; q < 4; q++) c[mi][ni][q] = 0.f;

    // ---- hoisted loader state (rows for i-th chunk: row0 + 32i; src stride 131072B,
    //      smem stride 4096B; swizzle invariant under row += 32) ----
    const int row0 = tid >> 3;           // 0..31
    const int c40 = tid & 7;
    const char* pA = (const char*)(A + (size_t)(m0 + row0) * D_ + c40 * 4);
    const char* pB = (const char*)(W + (size_t)(n0 + row0) * D_ + c40 * 4);
    const uint32_t dOff0 = sb + row0 * 128 + ((c40 * 16) ^ ((row0 & 3) << 5));
    uint32_t ldOff = 0;                  // stage ring offset for loads

    auto load_stage = [&]() {
        uint32_t da = dOff0 + ldOff;
#pragma unroll
        for (int i = 0; i < 4; i++) {
            cp16(da + i * 4096,                    pA + (size_t)i * 131072);
            cp16(da + TILE_FLOATS * 4 + i * 4096,  pB + (size_t)i * 131072);
        }
        asm volatile("cp.async.commit_group;" ::: "memory");
        pA += BKt * 4;
        pB += BKt * 4;
        ldOff = (ldOff == RING_TOP) ? 0u : ldOff + STAGE_BYTES;
    };

    load_stage();
    load_stage();
    asm volatile("cp.async.wait_group 1;" ::: "memory");
    __syncthreads();

    // hoisted fragment word offsets: q_j = ((8j) ^ sw) + 2*lc  (== (8j + 2lc) ^ sw)
    const int sw = (lr & 3) << 3;
    int qof[4];
#pragma unroll
    for (int j = 0; j < 4; j++) qof[j] = ((8 * j) ^ sw) + 2 * lc;

    uint32_t cOff = 0;                   // stage ring offset for compute
    for (int kt = 0; kt < NIT; kt++) {
        if (kt + 2 < NIT) load_stage();

        const float* As = (const float*)((const char*)smf + cOff);
        const float* Bs = As + TILE_FLOATS;
        const float* Arow = As + (wm * 32 + lr) * 32;
        const float* Brow = Bs + (wn * 64 + lr) * 32;
#pragma unroll
        for (int j = 0; j < 4; j++) {
            const int q = qof[j];
            uint32_t a[2][4], bf[8][2];
#pragma unroll
            for (int mi = 0; mi < 2; mi++) {
                float2 av0 = *(const float2*)(Arow + (mi * 16) * 32 + q);
                float2 av1 = *(const float2*)(Arow + (mi * 16 + 8) * 32 + q);
                a[mi][0] = U32F(av0.x);
                a[mi][2] = U32F(av0.y);
                a[mi][1] = U32F(av1.x);
                a[mi][3] = U32F(av1.y);
            }
#pragma unroll
            for (int ni = 0; ni < 8; ni++) {
                float2 bv = *(const float2*)(Brow + (ni * 8) * 32 + q);
                bf[ni][0] = U32F(bv.x);
                bf[ni][1] = U32F(bv.y);
            }
#pragma unroll
            for (int mi = 0; mi < 2; mi++)
#pragma unroll
                for (int ni = 0; ni < 8; ni++)
                    mma_tf32(c[mi][ni], a[mi], bf[ni]);
        }

        if (kt < NIT - 1) {
            if (kt + 2 < NIT) asm volatile("cp.async.wait_group 1;" ::: "memory");
            else              asm volatile("cp.async.wait_group 0;" ::: "memory");
            __syncthreads();
            cOff = (cOff == RING_TOP) ? 0u : cOff + STAGE_BYTES;
        }
    }
}

// Fused r/k/v GEMMs: blockIdx.z selects mode 0(sigmoid->g_R) 1(exp->g_EK) 2(->g_V)
__global__ void __launch_bounds__(256, 2)
gemm_qkv()
{
    extern __shared__ float smf[];
    uint32_t sb = smem_u32(smf);
    const int mode = blockIdx.z;
    const int m0 = blockIdx.y * 128;
    const int n0 = blockIdx.x * 128;
    const float* A = (mode == 0) ? g_XR : (mode == 1) ? g_XK : g_XV;
    const float* W = (mode == 0) ? g_Wr : (mode == 1) ? g_Wk : g_Wv;
    float* C = (mode == 0) ? g_R : (mode == 1) ? g_EK : g_V;

    float c[2][8][4];
    gemm_body(A, W, smf, sb, m0, n0, c);

    const int lane = threadIdx.x & 31;
    const int wid = threadIdx.x >> 5;
    const int lr = lane >> 2, lc = lane & 3;
    const int wm = wid & 3, wn = wid >> 2;
#pragma unroll
    for (int mi = 0; mi < 2; mi++) {
#pragma unroll
        for (int half = 0; half < 2; half++) {
            int m = m0 + wm * 32 + mi * 16 + lr + half * 8;
            float* crow = C + (size_t)m * D_ + n0 + wn * 64 + lc * 2;
#pragma unroll
            for (int ni = 0; ni < 8; ni++) {
                float v0 = c[mi][ni][half * 2 + 0];
                float v1 = c[mi][ni][half * 2 + 1];
                float2 o;
                if (mode == 0) {
                    o.x = 1.f / (1.f + __expf(-v0));
                    o.y = 1.f / (1.f + __expf(-v1));
                } else if (mode == 1) {
                    o.x = __expf(v0); o.y = __expf(v1);
                } else {
                    o.x = v0; o.y = v1;
                }
                *(float2*)(crow + ni * 8) = o;
            }
        }
    }
}

// Final GEMM: out = (scan_out normalized) @ (gamma⊙Wo)^T, GN folded algebraically
__global__ void __launch_bounds__(256, 2)
gemm_o(float* __restrict__ Cout)
{
    extern __shared__ float smf[];
    uint32_t sb = smem_u32(smf);
    const int m0 = blockIdx.y * 128;
    const int n0 = blockIdx.x * 128;

    float c[2][8][4];
    gemm_body(g_XR, g_Wg, smf, sb, m0, n0, c);

    const int lane = threadIdx.x & 31;
    const int wid = threadIdx.x >> 5;
    const int lr = lane >> 2, lc = lane & 3;
    const int wm = wid & 3, wn = wid >> 2;

    int b = m0 / T_;
    float mu = g_stats[2 * b];
    float rstd = g_stats[2 * b + 1];
#pragma unroll
    for (int mi = 0; mi < 2; mi++) {
#pragma unroll
        for (int half = 0; half < 2; half++) {
            int m = m0 + wm * 32 + mi * 16 + lr + half * 8;
            float* crow = Cout + (size_t)m * D_ + n0 + wn * 64 + lc * 2;
#pragma unroll
            for (int ni = 0; ni < 8; ni++) {
                float v0 = c[mi][ni][half * 2 + 0];
                float v1 = c[mi][ni][half * 2 + 1];
                int n = n0 + wn * 64 + ni * 8 + lc * 2;
                float2 o;
                o.x = v0 * rstd + (g_c2[n + 0] - mu * rstd * g_c1[n + 0]);
                o.y = v1 * rstd + (g_c2[n + 1] - mu * rstd * g_c1[n + 1]);
                *(float2*)(crow + ni * 8) = o;
            }
        }
    }
}

// -------------------- 3) chunk-parallel WKV scan --------------------
__global__ void scan_part1(const float* __restrict__ decay)
{
    int g = blockIdx.x * blockDim.x + threadIdx.x;
    int c = g & 1023;
    int cb = g >> 10;
    int b = cb & 7;
    int chunk = cb >> 3;

    float w = __expf(-__expf(decay[c]));
    const float* pEK = g_EK + ((size_t)(b * T_ + chunk * L_)) * D_ + c;
    const float* pV  = g_V  + ((size_t)(b * T_ + chunk * L_)) * D_ + c;

    float num = 0.f, den = 0.f;
#pragma unroll 4
    for (int t = 0; t < L_; t++) {
        float ek = pEK[(size_t)t * D_];
        float v  = pV [(size_t)t * D_];
        num = num * w + ek * v;
        den = den * w + ek;
    }
    g_locN[g] = num;
    g_locD[g] = den;
}

__global__ void scan_part2(const float* __restrict__ state, const float* __restrict__ decay)
{
    int g = blockIdx.x * blockDim.x + threadIdx.x;     // 0..8191
    int c = g & 1023;
    int b = g >> 10;
    float wL = __expf(-__expf(decay[c]) * (float)L_);
    float cn = state[((b << 10) + c) * 3 + 0];
    float cd = state[((b << 10) + c) * 3 + 1];
#pragma unroll
    for (int chunk = 0; chunk < CH_; chunk++) {
        int idx = ((chunk << 3) + b) * 1024 + c;
        g_carN[idx] = cn;
        g_carD[idx] = cd;
        cn = cn * wL + g_locN[idx];
        cd = cd * wL + g_locD[idx];
    }
}

__global__ void scan_part3(const float* __restrict__ decay, const float* __restrict__ first)
{
    int g = blockIdx.x * blockDim.x + threadIdx.x;
    int c = g & 1023;
    int cb = g >> 10;
    int b = cb & 7;
    int chunk = cb >> 3;

    float w  = __expf(-__expf(decay[c]));
    float eu = __expf(first[c]);
    float num = g_carN[g];
    float den = g_carD[g];

    size_t base = ((size_t)(b * T_ + chunk * L_)) * D_;
    const float* pR  = g_R  + base + c;
    const float* pEK = g_EK + base + c;
    const float* pV  = g_V  + base + c;
    int cp = (c & ~7) | (2 * (c & 3) + ((c >> 2) & 1));   // permuted column for GEMM-4 input
    float*       pO  = g_XR + base + cp;

    float sum = 0.f, sq = 0.f;
#pragma unroll 4
    for (int t = 0; t < L_; t++) {
        float ek = pEK[(size_t)t * D_];
        float v  = pV [(size_t)t * D_];
        float r  = pR [(size_t)t * D_];
        float ee = eu * ek;
        float wkv = __fdividef(num + ee * v, den + ee + EPS_WKV);
        float o = tf32r(r * wkv);
        pO[(size_t)t * D_] = o;
        sum += o;
        sq  += o * o;
        num = num * w + ek * v;
        den = den * w + ek;
    }
#pragma unroll
    for (int off = 16; off; off >>= 1) {
        sum += __shfl_down_sync(0xffffffffu, sum, off);
        sq  += __shfl_down_sync(0xffffffffu, sq,  off);
    }
    if ((threadIdx.x & 31) == 0) {
        int wg = g >> 5;
        g_part[wg * 2 + 0] = sum;
        g_part[wg * 2 + 1] = sq;
    }
}

__global__ void stats_kernel()
{
    int b = blockIdx.x;
    int lane = threadIdx.x;
    float s = 0.f, q = 0.f;
#pragma unroll
    for (int chunk = 0; chunk < CH_; chunk++) {
        int idx = chunk * 256 + b * 32 + lane;
        s += g_part[idx * 2 + 0];
        q += g_part[idx * 2 + 1];
    }
#pragma unroll
    for (int off = 16; off; off >>= 1) {
        s += __shfl_down_sync(0xffffffffu, s, off);
        q += __shfl_down_sync(0xffffffffu, q, off);
    }
    if (lane == 0) {
        const float N = (float)(T_ * D_);
        float mu = s / N;
        float var = q / N - mu * mu;
        g_stats[2 * b + 0] = mu;
        g_stats[2 * b + 1] = rsqrtf(var + EPS_GN);
    }
}

// -------------------- launch --------------------
extern "C" void kernel_launch(void* const* d_in, const int* in_sizes, int n_in,
                              void* d_out, int out_size)
{
    (void)in_sizes; (void)n_in; (void)out_size;
    const float* x     = (const float*)d_in[0];
    const float* state = (const float*)d_in[1];
    const float* Wr    = (const float*)d_in[2];
    const float* Wk    = (const float*)d_in[3];
    const float* Wv    = (const float*)d_in[4];
    const float* Wo    = (const float*)d_in[5];
    const float* mr    = (const float*)d_in[6];
    const float* mk    = (const float*)d_in[7];
    const float* mv    = (const float*)d_in[8];
    const float* decay = (const float*)d_in[9];
    const float* first = (const float*)d_in[10];
    const float* gam   = (const float*)d_in[11];
    const float* bet   = (const float*)d_in[12];
    float* out = (float*)d_out;

    cudaFuncSetAttribute(gemm_qkv, cudaFuncAttributeMaxDynamicSharedMemorySize, SMEM_SZ);
    cudaFuncSetAttribute(gemm_o,   cudaFuncAttributeMaxDynamicSharedMemorySize, SMEM_SZ);

    const int MIX_BLOCKS = (M_ * D_ / 8) / 256;
    const int RW_BLOCKS  = (D_ * D_ / 8) / 256;
    const int S13_BLOCKS = (CH_ * B_ * 1024) / 256;
    const int S2_BLOCKS  = (B_ * 1024) / 256;

    round_w<<<RW_BLOCKS, 256>>>(Wr, Wk, Wv);
    prep_wo<<<D_, 256>>>(Wo, gam, bet);
    mix_kernel<<<MIX_BLOCKS, 256>>>(x, state, mr, mk, mv);

    dim3 gq(D_ / 128, M_ / 128, 3);          // fused r/k/v GEMMs
    gemm_qkv<<<gq, 256, SMEM_SZ>>>();

    scan_part1<<<S13_BLOCKS, 256>>>(decay);
    scan_part2<<<S2_BLOCKS, 256>>>(state, decay);
    scan_part3<<<S13_BLOCKS, 256>>>(decay, first);
    stats_kernel<<<8, 32>>>();

    dim3 gg(D_ / 128, M_ / 128);
    gemm_o<<<gg, 256, SMEM_SZ>>>(out);
}